// round 9
// baseline (speedup 1.0000x reference)
#include <cuda_runtime.h>
#include <cstdint>

#define B_N  32
#define C_IN 64
#define H    192
#define W    192
#define HO   190
#define WO   190
#define OC   128
#define HW   (H*W)

#define XSS 72            // Xs2 row stride in floats (conflict-free LDS.64 pattern)

// ---------------- device scratch (no allocations allowed) -------------------
__device__ float g_valid[B_N][4];
__device__ float g_bsum[B_N][OC];
// A-fragment-ordered weights: [tap][chunk][slab(2)][oct(4)][lane(32)][4]
__device__ __align__(16) float g_wA[9 * 8 * 2 * 4 * 32 * 4];

__device__ __forceinline__ bool is_nan_bits(float v) {
    unsigned u = __float_as_uint(v);
    return (u & 0x7fffffffu) > 0x7f800000u;
}
__device__ __forceinline__ unsigned f2tf32(float v) {
    unsigned r;
    asm("cvt.rna.tf32.f32 %0, %1;" : "=r"(r) : "f"(v));
    return r;
}

#define MMA_TF32(d, a, b0, b1) \
    asm volatile("mma.sync.aligned.m16n8k8.row.col.f32.tf32.tf32.f32 " \
        "{%0,%1,%2,%3},{%4,%5,%6,%7},{%8,%9},{%0,%1,%2,%3};" \
        : "+f"((d)[0]), "+f"((d)[1]), "+f"((d)[2]), "+f"((d)[3]) \
        : "r"((a).x), "r"((a).y), "r"((a).z), "r"((a).w), "r"(b0), "r"(b1))

// ---------------- setup: validity + bias + fragment-ordered weights ---------
// blocks 0..287: weights, block 288: validity + bias sums.
__global__ void setup_kernel(const float* __restrict__ x,
                             const float* __restrict__ w,
                             const float* __restrict__ bias) {
    int t = threadIdx.x;
    if (blockIdx.x < 288) {
        int i = blockIdx.x * 256 + t;            // 0..73727
        int a     = i & 3;
        int lane  = (i >> 2) & 31;
        int oct   = (i >> 7) & 3;
        int slab  = (i >> 9) & 1;
        int chunk = (i >> 10) & 7;
        int tap   = i >> 13;                     // ky*3 + kx
        // A frag (m16n8k8 tf32): a0:(m,k) a1:(m+8,k) a2:(m,k+4) a3:(m+8,k+4)
        int row  = (lane >> 2) + (a & 1) * 8;
        int kcol = (lane & 3) + (a >> 1) * 4;
        int oc   = slab * 64 + oct * 16 + row;
        int c    = chunk * 8 + kcol;             // raw channel index
        int f = c & 3, j = c >> 2;
        float v = w[f * 18432 + oc * 144 + j * 9 + tap];
        g_wA[i] = __uint_as_float(f2tf32(v));
    } else {
        __shared__ float sval[B_N][4];
        if (t < B_N * 4) {
            int b = t >> 2, f = t & 3;
            float v = x[(size_t)(b * C_IN + f) * HW];   // marker at (0,0)
            float val = is_nan_bits(v) ? 0.f : 1.f;
            g_valid[b][f] = val;
            sval[b][f] = val;
        }
        __syncthreads();
        for (int i = t; i < B_N * OC; i += 256) {
            int b = i >> 7, oc = i & 127;
            float s = 0.f;
#pragma unroll
            for (int f = 0; f < 4; f++) s += sval[b][f] * bias[f * OC + oc];
            g_bsum[b][oc] = s;
        }
    }
}

// ---------------- main conv: tf32 mma.sync implicit GEMM --------------------
// grid = (2 x-tiles, 190 rows, 32 batches), block = 256 (8 warps)
// Block tile: 128 oc x 96 px. Warp: 64 oc x 24 px (slab=warp&1, quarter=warp>>1).
__global__ void __launch_bounds__(256, 2)
conv_kernel(const float* __restrict__ x, float* __restrict__ out) {
    __shared__ float Xs2[98][XSS];            // px-major, k-pair-packed channels
    __shared__ float vm[4];

    const int x0 = blockIdx.x * 94;           // 0 or 94 (tiles overlap 2 px)
    const int y  = blockIdx.y;
    const int b  = blockIdx.z;

    const int t    = threadIdx.x;
    const int warp = t >> 5;
    const int lane = t & 31;
    const int slab = warp & 1;                // oc half (64 oc)
    const int nb   = (warp >> 1) * 24;        // px quarter

    if (t < 4) vm[t] = g_valid[b][t];

    const float* xb = x + (size_t)b * C_IN * HW + (size_t)y * W + x0;

    // acc[oct][nt][4]
    float acc[4][3][4];
#pragma unroll
    for (int o = 0; o < 4; o++)
#pragma unroll
        for (int nt = 0; nt < 3; nt++)
#pragma unroll
            for (int q = 0; q < 4; q++) acc[o][nt][q] = 0.f;

    const uint4* wbase = reinterpret_cast<const uint4*>(g_wA);

#pragma unroll 1
    for (int ky = 0; ky < 3; ky++) {
        // ---- stage input row y+ky: 64 ch x 98 px, pair-packed -------------
        // item: pair p (chunk=p>>2, kp=p&3 -> channels c0=chunk*8+kp, c0+4), px
        __syncthreads();
        {
            const float* xrow = xb + (size_t)ky * W;
#pragma unroll
            for (int q = 0; q < 13; q++) {
                int s = q * 256 + t;
                if (s < 3136) {                       // 32 pairs * 98 px
                    int p  = s / 98;
                    int px = s - p * 98;
                    int chunk = p >> 2, kp = p & 3;
                    int c0 = chunk * 8 + kp;
                    float vmf = vm[kp];
                    float v0 = xrow[(size_t)c0 * HW + px];
                    float v1 = xrow[(size_t)(c0 + 4) * HW + px];
                    v0 = is_nan_bits(v0) ? 0.f : v0;
                    v1 = is_nan_bits(v1) ? 0.f : v1;
                    float2 pr;
                    pr.x = __uint_as_float(f2tf32(v0 * vmf));
                    pr.y = __uint_as_float(f2tf32(v1 * vmf));
                    *reinterpret_cast<float2*>(&Xs2[px][chunk * 8 + 2 * kp]) = pr;
                }
            }
        }
        __syncthreads();

#pragma unroll 1
        for (int kx = 0; kx < 3; kx++) {
            const int tap = ky * 3 + kx;
            // uint4 index: tap*2048 + chunk*256 + slab*128 + oct*32 + lane
            const uint4* wp = wbase + tap * 2048 + slab * 128 + lane;
            const float* xr = &Xs2[kx + nb + (lane >> 2)][2 * (lane & 3)];

            uint4 an0 = wp[0];                 // prefetch chunk 0, all 4 octs
            uint4 an1 = wp[32];
            uint4 an2 = wp[64];
            uint4 an3 = wp[96];

#pragma unroll 1
            for (int ch = 0; ch < 8; ch++) {
                uint4 a0 = an0, a1 = an1, a2 = an2, a3 = an3;
                if (ch < 7) {
                    const uint4* wn = wp + (ch + 1) * 256;
                    an0 = wn[0];
                    an1 = wn[32];
                    an2 = wn[64];
                    an3 = wn[96];
                }
                const float* xc = xr + ch * 8;
#pragma unroll
                for (int nt = 0; nt < 3; nt++) {
                    float2 bp = *reinterpret_cast<const float2*>(xc + nt * (8 * XSS));
                    unsigned b0 = __float_as_uint(bp.x);
                    unsigned b1 = __float_as_uint(bp.y);
                    MMA_TF32(acc[0][nt], a0, b0, b1);
                    MMA_TF32(acc[1][nt], a1, b0, b1);
                    MMA_TF32(acc[2][nt], a2, b0, b1);
                    MMA_TF32(acc[3][nt], a3, b0, b1);
                }
            }
        }
    }

    // ---- epilogue: bias + store ------------------------------------------
    // D frag: d0:(m,2c) d1:(m,2c+1) d2:(m+8,2c) d3:(m+8,2c+1)
    const int mrow = lane >> 2;
    const int ncol = 2 * (lane & 3);
#pragma unroll
    for (int oct = 0; oct < 4; oct++) {
        int ocb = slab * 64 + oct * 16 + mrow;
        float bsA = g_bsum[b][ocb];
        float bsB = g_bsum[b][ocb + 8];
        float* o0 = out + ((size_t)(b * OC + ocb) * HO + y) * WO + x0 + nb + ncol;
        float* o1 = o0 + (size_t)8 * HO * WO;
#pragma unroll
        for (int nt = 0; nt < 3; nt++) {
            *reinterpret_cast<float2*>(o0 + nt * 8) =
                make_float2(acc[oct][nt][0] + bsA, acc[oct][nt][1] + bsA);
            *reinterpret_cast<float2*>(o1 + nt * 8) =
                make_float2(acc[oct][nt][2] + bsB, acc[oct][nt][3] + bsB);
        }
    }
}

// ---------------- launch -----------------------------------------------------
extern "C" void kernel_launch(void* const* d_in, const int* in_sizes, int n_in,
                              void* d_out, int out_size) {
    const float* x    = (const float*)d_in[0];
    const float* w    = (const float*)d_in[1];
    const float* bias = (const float*)d_in[2];
    float* out = (float*)d_out;

    setup_kernel<<<289, 256>>>(x, w, bias);
    conv_kernel<<<dim3(2, HO, B_N), 256>>>(x, out);
}

// round 10
// speedup vs baseline: 1.1347x; 1.1347x over previous
#include <cuda_runtime.h>
#include <cstdint>

#define B_N  32
#define C_IN 64
#define H    192
#define W    192
#define HO   190
#define WO   190
#define OC   128
#define HW   (H*W)

#define XR   100          // Xraw row stride (floats); 100%32=4 -> LDS.128 col reads conflict-free
#define XSS  72           // Xs2 row stride; 72%32=8 -> mainloop LDS.64 conflict-free
#define PXW  100          // staged window width (25 float4 per channel, no tail)

// ---------------- device scratch (no allocations allowed) -------------------
__device__ float g_valid[B_N][4];
__device__ float g_bsum[B_N][OC];
// A-fragment-ordered weights: [tap][chunk][slab(4)][oct(2)][lane(32)][4]
__device__ __align__(16) float g_wA[9 * 8 * 4 * 2 * 32 * 4];

__device__ __forceinline__ bool is_nan_bits(float v) {
    unsigned u = __float_as_uint(v);
    return (u & 0x7fffffffu) > 0x7f800000u;
}
__device__ __forceinline__ unsigned f2tf32(float v) {
    unsigned r;
    asm("cvt.rna.tf32.f32 %0, %1;" : "=r"(r) : "f"(v));
    return r;
}
__device__ __forceinline__ unsigned smem_u32(const void* p) {
    unsigned a;
    asm("{ .reg .u64 t; cvta.to.shared.u64 t, %1; cvt.u32.u64 %0, t; }" : "=r"(a) : "l"(p));
    return a;
}

#define MMA_TF32(d, a, b0, b1) \
    asm volatile("mma.sync.aligned.m16n8k8.row.col.f32.tf32.tf32.f32 " \
        "{%0,%1,%2,%3},{%4,%5,%6,%7},{%8,%9},{%0,%1,%2,%3};" \
        : "+f"((d)[0]), "+f"((d)[1]), "+f"((d)[2]), "+f"((d)[3]) \
        : "r"((a).x), "r"((a).y), "r"((a).z), "r"((a).w), "r"(b0), "r"(b1))

// ---------------- setup: validity + bias + fragment-ordered weights ---------
__global__ void setup_kernel(const float* __restrict__ x,
                             const float* __restrict__ w,
                             const float* __restrict__ bias) {
    int t = threadIdx.x;
    if (blockIdx.x < 288) {
        int i = blockIdx.x * 256 + t;            // 0..73727
        int a    = i & 3;
        int lane = (i >> 2) & 31;
        int oct  = (i >> 7) & 1;
        int slab = (i >> 8) & 3;
        int chunk= (i >> 10) & 7;
        int tap  = i >> 13;                      // ky*3 + kx
        // A frag (m16n8k8 tf32): a0:(m,k) a1:(m+8,k) a2:(m,k+4) a3:(m+8,k+4)
        int row  = (lane >> 2) + (a & 1) * 8;
        int kcol = (lane & 3) + (a >> 1) * 4;
        int oc   = slab * 32 + oct * 16 + row;
        int c    = chunk * 8 + kcol;             // raw channel index
        int f = c & 3, j = c >> 2;
        float v = w[f * 18432 + oc * 144 + j * 9 + tap];
        g_wA[i] = __uint_as_float(f2tf32(v));
    } else {
        __shared__ float sval[B_N][4];
        if (t < B_N * 4) {
            int b = t >> 2, f = t & 3;
            float v = x[(size_t)(b * C_IN + f) * HW];   // marker at (0,0)
            float val = is_nan_bits(v) ? 0.f : 1.f;
            g_valid[b][f] = val;
            sval[b][f] = val;
        }
        __syncthreads();
        for (int i = t; i < B_N * OC; i += 256) {
            int b = i >> 7, oc = i & 127;
            float s = 0.f;
#pragma unroll
            for (int f = 0; f < 4; f++) s += sval[b][f] * bias[f * OC + oc];
            g_bsum[b][oc] = s;
        }
    }
}

// ---------------- main conv: tf32 mma.sync implicit GEMM --------------------
// grid = (2 x-tiles, 190 rows, 32 batches), block = 256 (8 warps)
// Block tile: 128 oc x 96 px. Warp: 32 oc x 48 px (slab=warp>>1, half=warp&1).
__global__ void __launch_bounds__(256, 2)
conv_kernel(const float* __restrict__ x, float* __restrict__ out) {
    extern __shared__ float smem[];
    float* Xraw = smem;                        // [64][XR]
    float* Xs2  = smem + C_IN * XR;            // [PXW][XSS] px-major, pair-packed
    float* vm   = smem + C_IN * XR + PXW * XSS;
    const unsigned rawb = smem_u32(Xraw);

    const int x0    = blockIdx.x * 94;         // output x start (tiles overlap 2)
    const int px0   = blockIdx.x * 92;         // staged window start (16B aligned)
    const int pxoff = blockIdx.x * 2;          // x0 - px0
    const int y  = blockIdx.y;
    const int b  = blockIdx.z;

    const int t    = threadIdx.x;
    const int warp = t >> 5;
    const int lane = t & 31;
    const int slab = warp >> 1;                // oc slab of 32
    const int nb   = (warp & 1) * 48;          // px half

    if (t < 4) vm[t] = g_valid[b][t];

    const float* xwin = x + (size_t)b * C_IN * HW + (size_t)y * W + px0;

    // cp.async stage of one input row (all 64 ch x 100 px) into Xraw
    auto stage = [&](int ky) {
        const float* xrow = xwin + (size_t)ky * W;
#pragma unroll
        for (int q = 0; q < 7; q++) {
            int i = q * 256 + t;
            if (i < 1600) {                    // 64 ch * 25 float4
                int c = i / 25, seg = i - c * 25;
                const float* src = xrow + (size_t)c * HW + seg * 4;
                unsigned dst = rawb + (unsigned)(c * XR + seg * 4) * 4u;
                asm volatile("cp.async.ca.shared.global [%0], [%1], 16;"
                             :: "r"(dst), "l"(src) : "memory");
            }
        }
        asm volatile("cp.async.commit_group;" ::: "memory");
    };

    // acc[oct][nt][4]
    float acc[2][6][4];
#pragma unroll
    for (int o = 0; o < 2; o++)
#pragma unroll
        for (int nt = 0; nt < 6; nt++)
#pragma unroll
            for (int q = 0; q < 4; q++) acc[o][nt][q] = 0.f;

    const uint4* wbase = reinterpret_cast<const uint4*>(g_wA);

    stage(0);

#pragma unroll 1
    for (int ky = 0; ky < 3; ky++) {
        asm volatile("cp.async.wait_group 0;" ::: "memory");
        __syncthreads();

        // ---- transpose Xraw -> Xs2 with nan-zero, mask, tf32 round --------
        {
            const int c    = ((/*chalf*/ 0) * 32) + lane;   // chalf added per item
#pragma unroll 1
            for (int it = warp; it < 50; it += 8) {
                int chalf = it & 1, qq = it >> 1;           // qq = px quad 0..24
                int cc = chalf * 32 + lane;
                float vmf = vm[cc & 3];
                float4 v4 = *reinterpret_cast<const float4*>(Xraw + cc * XR + qq * 4);
                int cpos = (cc >> 3) * 8 + 2 * (cc & 3) + ((cc >> 2) & 1);
                float vv[4] = {v4.x, v4.y, v4.z, v4.w};
#pragma unroll
                for (int j = 0; j < 4; j++) {
                    float v = vv[j];
                    v = is_nan_bits(v) ? 0.f : v;
                    Xs2[(4 * qq + j) * XSS + cpos] = __uint_as_float(f2tf32(v * vmf));
                }
            }
            (void)c;
        }
        __syncthreads();

        if (ky < 2) stage(ky + 1);             // overlap next row's loads with MMAs

        // ---- MMAs over 3 kx taps x 8 channel chunks -----------------------
#pragma unroll 1
        for (int kx = 0; kx < 3; kx++) {
            const int tap = ky * 3 + kx;
            const uint4* wp = wbase + (size_t)(tap * 32 + slab) * 64 + lane;
            const float* xr = Xs2 + (kx + pxoff + nb + (lane >> 2)) * XSS + 2 * (lane & 3);

            uint4 an0 = wp[0];                 // prefetch chunk 0
            uint4 an1 = wp[32];

#pragma unroll 1
            for (int ch = 0; ch < 8; ch++) {
                uint4 a0 = an0, a1 = an1;
                if (ch < 7) {
                    an0 = wp[(ch + 1) * 256];
                    an1 = wp[(ch + 1) * 256 + 32];
                }
                const float* xc = xr + ch * 8;
#pragma unroll
                for (int nt = 0; nt < 6; nt++) {
                    float2 bp = *reinterpret_cast<const float2*>(xc + nt * (8 * XSS));
                    unsigned b0 = __float_as_uint(bp.x);
                    unsigned b1 = __float_as_uint(bp.y);
                    MMA_TF32(acc[0][nt], a0, b0, b1);
                    MMA_TF32(acc[1][nt], a1, b0, b1);
                }
            }
        }
    }

    // ---- epilogue: bias + store ------------------------------------------
    // D frag: d0:(m,2c) d1:(m,2c+1) d2:(m+8,2c) d3:(m+8,2c+1)
    const int mrow = lane >> 2;
    const int ncol = 2 * (lane & 3);
#pragma unroll
    for (int oct = 0; oct < 2; oct++) {
        int ocb = slab * 32 + oct * 16 + mrow;
        float bsA = g_bsum[b][ocb];
        float bsB = g_bsum[b][ocb + 8];
        float* o0 = out + ((size_t)(b * OC + ocb) * HO + y) * WO + x0 + nb + ncol;
        float* o1 = o0 + (size_t)8 * HO * WO;
#pragma unroll
        for (int nt = 0; nt < 6; nt++) {
            *reinterpret_cast<float2*>(o0 + nt * 8) =
                make_float2(acc[oct][nt][0] + bsA, acc[oct][nt][1] + bsA);
            *reinterpret_cast<float2*>(o1 + nt * 8) =
                make_float2(acc[oct][nt][2] + bsB, acc[oct][nt][3] + bsB);
        }
    }
}

// ---------------- launch -----------------------------------------------------
extern "C" void kernel_launch(void* const* d_in, const int* in_sizes, int n_in,
                              void* d_out, int out_size) {
    const float* x    = (const float*)d_in[0];
    const float* w    = (const float*)d_in[1];
    const float* bias = (const float*)d_in[2];
    float* out = (float*)d_out;

    const int SMEM_BYTES = (C_IN * XR + PXW * XSS + 8) * 4;   // ~54.5 KB
    cudaFuncSetAttribute(conv_kernel,
                         cudaFuncAttributeMaxDynamicSharedMemorySize, SMEM_BYTES);

    setup_kernel<<<289, 256>>>(x, w, bias);
    conv_kernel<<<dim3(2, HO, B_N), 256, SMEM_BYTES>>>(x, out);
}